// round 14
// baseline (speedup 1.0000x reference)
#include <cuda_runtime.h>
#include <math.h>

#define BB   64
#define TDD  1024
#define TQQ  32
#define EE   384
#define HH   256
#define GG   1536   // 2 dirs x 3H
#define DHH  512
#define VV   50000
#define EPSF 1e-12f

// ------------------------- device scratch (no allocations) -------------------------
__device__ float g_xw  [(size_t)BB*TDD*GG];   // doc xw, fwd[0,768) bwd[768,1536)
__device__ float g_xwq [(size_t)BB*TQQ*GG];   // qry xw
__device__ float g_doch[(size_t)BB*TDD*DHH];  // doc hidden (fwd|bwd), masked-zero
__device__ float g_qryh[(size_t)BB*TQQ*DHH];  // qry hidden, masked-zero
__device__ float2 g_h2d[2*2*BB*HH];           // {h, step-tag} pairs [dir][par][b][u]
__device__ float2 g_h2q[2*2*BB*HH];
__device__ float g_scores[(size_t)BB*TDD*TQQ];
__device__ float g_colmax[BB*TQQ];
__device__ float g_colsum[BB*TQQ];
__device__ float g_betasum[BB*TQQ];
__device__ float g_wq[BB*TQQ];
__device__ float g_sums[(size_t)BB*VV];
__device__ unsigned long long g_key[BB];

// ------------------------- packed f32x2 helpers -------------------------
union U2 { unsigned long long u; float2 f; };

__device__ __forceinline__ void fma2(unsigned long long &d, unsigned long long a, unsigned long long b){
    asm("fma.rn.f32x2 %0, %1, %2, %0;" : "+l"(d) : "l"(a), "l"(b));
}
__device__ __forceinline__ unsigned long long dup2(float x){
    U2 t; t.f.x = x; t.f.y = x; return t.u;
}

// ------------------------- relaxed 8B atomic pair helpers -------------------------
__device__ __forceinline__ unsigned long long ld_rlx64(const float2* p){
    unsigned long long v;
    asm volatile("ld.relaxed.gpu.global.b64 %0, [%1];" : "=l"(v) : "l"(p) : "memory");
    return v;
}
__device__ __forceinline__ void st_rlx64(float2* p, unsigned long long v){
    asm volatile("st.relaxed.gpu.global.b64 [%0], %1;" :: "l"(p), "l"(v) : "memory");
}
__device__ __forceinline__ float tanh_fast(float x){
    float y;
    asm("tanh.approx.f32 %0, %1;" : "=f"(y) : "f"(x));
    return y;
}
__device__ __forceinline__ float sigmoid_fast(float x){
    return 1.f / (1.f + __expf(-x));
}

// ------------------------- misc warp helpers -------------------------
__device__ __forceinline__ float wsum(float v){
#pragma unroll
    for (int o = 16; o; o >>= 1) v += __shfl_xor_sync(0xffffffffu, v, o);
    return v;
}
__device__ __forceinline__ float wmax(float v){
#pragma unroll
    for (int o = 16; o; o >>= 1) v = fmaxf(v, __shfl_xor_sync(0xffffffffu, v, o));
    return v;
}

// ------------------------- reset -------------------------
__global__ __launch_bounds__(256) void k_reset(const int* __restrict__ docs, float* __restrict__ out){
    int i = blockIdx.x * 256 + threadIdx.x;               // grid 256x256 = 65536
    // pair buffers: [dir][par][16384]; par-0 tag 0 (valid zeros for step 0), par-1 tag -1
    int par = (i >> 14) & 1;
    float2 init = make_float2(0.f, par ? -1.f : 0.f);
    g_h2d[i] = init;
    g_h2q[i] = init;
    if (i < 2048) g_betasum[i] = 0.f;
    if (i < 128)  out[i] = 0.f;
    if (i < 64)   g_key[i] = 0ull;
    int b = i >> 10;                                      // scatter-zero touched vocab slots
    g_sums[(size_t)b * VV + docs[i]] = 0.f;
}

// ------------------------- xw GEMM: gather(emb) @ [Wf;Wb]^T + bias -------------------------
// 128x128 tile, 256 threads, 8x8 microtile on fma.rn.f32x2 (pairs over M, loaded as b64 LDS).
__global__ __launch_bounds__(256) void k_xw(const int* __restrict__ toks, int isdoc,
                                            const int* __restrict__ lens,
                                            const float* __restrict__ emb,
                                            const float* __restrict__ Wf, const float* __restrict__ Wb,
                                            const float* __restrict__ bf, const float* __restrict__ bb){
    __shared__ __align__(16) float As[32][132];   // [k][m]
    __shared__ __align__(16) float Ws[32][132];   // [k][n]
    __shared__ int tk[128];
    float* outp = isdoc ? g_xw : g_xwq;
    int tid = threadIdx.x;
    int m0 = blockIdx.x * 128, n0 = blockIdx.y * 128;
    if (isdoc){
        int b = m0 >> 10;
        if ((m0 & 1023) >= lens[b]) return;       // tile fully beyond doc len: rows stay 0, never read
    }
    const float* W; const float* bias;
    if (n0 < 768){ W = Wf + (size_t)n0 * EE;        bias = bf + n0; }
    else         { W = Wb + (size_t)(n0-768) * EE;  bias = bb + (n0-768); }
    if (tid < 128) tk[tid] = toks[m0 + tid];
    __syncthreads();

    int ty = tid >> 4, tx = tid & 15;             // rows ty*8..+7 (4 pairs), cols tx*8..+7
    int rr = tid & 127, kq0 = tid >> 7;           // fill: kq = kq0 + 2*i, i<4
    const float* arow = emb + (size_t)tk[rr] * EE;
    const float* wrow = W   + (size_t)rr * EE;

    U2 acc[4][8];                                 // [M-pair][N]
#pragma unroll
    for (int i = 0; i < 4; i++)
#pragma unroll
        for (int j = 0; j < 8; j++) acc[i][j].f = make_float2(0.f, 0.f);

    float4 ra[4], rw[4];
#pragma unroll
    for (int i = 0; i < 4; i++){
        ra[i] = *(const float4*)(arow + (kq0 + 2*i)*4);
        rw[i] = *(const float4*)(wrow + (kq0 + 2*i)*4);
    }

    for (int c = 0; c < 12; c++){
        __syncthreads();
#pragma unroll
        for (int i = 0; i < 4; i++){
            int kb = (kq0 + 2*i) * 4;
            As[kb+0][rr] = ra[i].x; As[kb+1][rr] = ra[i].y; As[kb+2][rr] = ra[i].z; As[kb+3][rr] = ra[i].w;
            Ws[kb+0][rr] = rw[i].x; Ws[kb+1][rr] = rw[i].y; Ws[kb+2][rr] = rw[i].z; Ws[kb+3][rr] = rw[i].w;
        }
        __syncthreads();
        if (c + 1 < 12){
            int kt = (c + 1) * 32;
#pragma unroll
            for (int i = 0; i < 4; i++){
                ra[i] = *(const float4*)(arow + kt + (kq0 + 2*i)*4);
                rw[i] = *(const float4*)(wrow + kt + (kq0 + 2*i)*4);
            }
        }
#pragma unroll 4
        for (int kk = 0; kk < 32; kk++){
            ulonglong2 A01 = *(const ulonglong2*)&As[kk][ty*8];       // 2 M-pairs, LDS.128
            ulonglong2 A23 = *(const ulonglong2*)&As[kk][ty*8 + 4];   // 2 M-pairs
            float4 w0 = *(const float4*)&Ws[kk][tx*8];
            float4 w1 = *(const float4*)&Ws[kk][tx*8 + 4];
            unsigned long long ap[4] = { A01.x, A01.y, A23.x, A23.y };
            unsigned long long wd[8] = { dup2(w0.x), dup2(w0.y), dup2(w0.z), dup2(w0.w),
                                         dup2(w1.x), dup2(w1.y), dup2(w1.z), dup2(w1.w) };
#pragma unroll
            for (int ip = 0; ip < 4; ip++)
#pragma unroll
                for (int j = 0; j < 8; j++) fma2(acc[ip][j].u, ap[ip], wd[j]);
        }
    }

    float4 bv0 = *(const float4*)(bias + tx*8);
    float4 bv1 = *(const float4*)(bias + tx*8 + 4);
    float bb8[8] = {bv0.x, bv0.y, bv0.z, bv0.w, bv1.x, bv1.y, bv1.z, bv1.w};
#pragma unroll
    for (int ip = 0; ip < 4; ip++){
        size_t r0 = (size_t)m0 + ty*8 + 2*ip;
        float4 o0 = make_float4(acc[ip][0].f.x + bb8[0], acc[ip][1].f.x + bb8[1],
                                acc[ip][2].f.x + bb8[2], acc[ip][3].f.x + bb8[3]);
        float4 o1 = make_float4(acc[ip][4].f.x + bb8[4], acc[ip][5].f.x + bb8[5],
                                acc[ip][6].f.x + bb8[6], acc[ip][7].f.x + bb8[7]);
        float4 o2 = make_float4(acc[ip][0].f.y + bb8[0], acc[ip][1].f.y + bb8[1],
                                acc[ip][2].f.y + bb8[2], acc[ip][3].f.y + bb8[3]);
        float4 o3 = make_float4(acc[ip][4].f.y + bb8[4], acc[ip][5].f.y + bb8[5],
                                acc[ip][6].f.y + bb8[6], acc[ip][7].f.y + bb8[7]);
        *(float4*)(outp + r0 * GG + n0 + tx*8)           = o0;
        *(float4*)(outp + r0 * GG + n0 + tx*8 + 4)       = o1;
        *(float4*)(outp + (r0 + 1) * GG + n0 + tx*8)     = o2;
        *(float4*)(outp + (r0 + 1) * GG + n0 + tx*8 + 4) = o3;
    }
}

// ------------------------- persistent bidirectional GRU recurrence -------------------------
// 128 CTAs = dir(2) x bslice(8: 8 batches) x jslice(8: 32 units). Whh register-stationary (f32x2).
// Sync: SELF-FLAGGING {h, step-tag} 8B pairs via relaxed b64 atomics. No flags, no releases,
// no fences: the successful poll IS the data load. Double-buffered by parity (skew <= 1 by
// dataflow). red double-buffered by parity -> single __syncthreads per step.
__global__ __launch_bounds__(256,1) void k_rnn(int isdoc, int T,
                                               const float* __restrict__ Whh_f, const float* __restrict__ bhh_f,
                                               const float* __restrict__ Whh_b, const float* __restrict__ bhh_b,
                                               const int* __restrict__ lens){
    int dir = blockIdx.x >> 6;
    int rem = blockIdx.x & 63;
    int bs  = rem >> 3;
    int js  = rem & 7;
    int tid = threadIdx.x;
    int u   = tid & 31;      // unit lane
    int ks  = tid >> 5;      // warp id = k-slice consumed = finalize batch-offset
    int b0  = bs * 8;
    int gu  = js * 32 + u;

    const float* xw  = isdoc ? g_xw   : g_xwq;
    float*       outh= isdoc ? g_doch : g_qryh;
    float2*      hp2 = (isdoc ? g_h2d : g_h2q) + (size_t)dir * 2 * BB * HH;  // [par][b][u]
    const float* Whh = dir ? Whh_b : Whh_f;
    const float* bhh = dir ? bhh_b : bhh_f;

    U2 w0p[16], w1p[16], w2p[16];
#pragma unroll
    for (int kk = 0; kk < 16; kk++){
        w0p[kk].f = *(const float2*)&Whh[(size_t)(gu)        * HH + ks*32 + kk*2];
        w1p[kk].f = *(const float2*)&Whh[(size_t)(HH + gu)   * HH + ks*32 + kk*2];
        w2p[kk].f = *(const float2*)&Whh[(size_t)(2*HH + gu) * HH + ks*32 + kk*2];
    }
    float bh0 = bhh[gu], bh1 = bhh[HH+gu], bh2 = bhh[2*HH+gu];
    int fb = b0 + ks;                     // finalize batch (fixed per thread)
    int mylen = lens[fb];
    int Tgrp = 0;
#pragma unroll
    for (int i = 0; i < 8; i++){ int l = lens[b0 + i]; Tgrp = (l > Tgrp) ? l : Tgrp; }

    __shared__ __align__(16) float hs2[8][8][32];    // [kslice][batch][kk]
    __shared__ float red[2][8][3][8][32];            // [parity][kslice][row][batch][unit]

    float hprev = 0.f;                    // h[fb][gu] carried in-register

    for (int s = 0; s < Tgrp; s++){
        // prefetch xw for this step (in flight across the poll)
        int xpos = dir ? ((s < mylen) ? (mylen - 1 - s) : 0) : s;
        const float* xp = xw + ((size_t)fb * T + xpos) * GG + dir * 768;
        float gr = __ldg(xp + gu);
        float gz = __ldg(xp + 256 + gu);
        float gn = __ldg(xp + 512 + gu);

        int p = s & 1;
        float tgt = (float)s;
        // poll the 8 self-flagged pairs this lane consumes: batch b0+bl, unit ks*32+u
        float2* pb = hp2 + (size_t)p * BB * HH + (size_t)b0 * HH + ks*32 + u;
        U2 pr[8];
#pragma unroll
        for (int bl = 0; bl < 8; bl++) pr[bl].u = ld_rlx64(pb + bl * HH);   // 8 independent
#pragma unroll
        for (int bl = 0; bl < 8; bl++){
            while (pr[bl].f.y != tgt) pr[bl].u = ld_rlx64(pb + bl * HH);
            hs2[ks][bl][u] = pr[bl].f.x;
        }
        __syncwarp();

        // partial dot products: this warp's 32-k slice, 8 batches, 3 gate rows (f32x2)
#pragma unroll
        for (int bl = 0; bl < 8; bl++){
            const float4* hp = (const float4*)&hs2[ks][bl][0];
            U2 A0, A1, A2;
            A0.f = make_float2(0.f,0.f); A1.f = make_float2(0.f,0.f); A2.f = make_float2(0.f,0.f);
#pragma unroll
            for (int k4 = 0; k4 < 8; k4++){
                float4 hv = hp[k4];
                U2 h01, h23;
                h01.f = make_float2(hv.x, hv.y);
                h23.f = make_float2(hv.z, hv.w);
                fma2(A0.u, h01.u, w0p[2*k4].u); fma2(A0.u, h23.u, w0p[2*k4+1].u);
                fma2(A1.u, h01.u, w1p[2*k4].u); fma2(A1.u, h23.u, w1p[2*k4+1].u);
                fma2(A2.u, h01.u, w2p[2*k4].u); fma2(A2.u, h23.u, w2p[2*k4+1].u);
            }
            red[p][ks][0][bl][u] = A0.f.x + A0.f.y;
            red[p][ks][1][bl][u] = A1.f.x + A1.f.y;
            red[p][ks][2][bl][u] = A2.f.x + A2.f.y;
        }
        __syncthreads();     // red[p] complete; WAR on red[p] protected by parity + this barrier

        // finalize: thread handles (batch=fb, unit=gu); hprev in register
        float hr = bh0, hz = bh1, hn = bh2;
#pragma unroll
        for (int k = 0; k < 8; k++){
            hr += red[p][k][0][ks][u]; hz += red[p][k][1][ks][u]; hn += red[p][k][2][ks][u];
        }
        float rg = sigmoid_fast(gr + hr);
        float zg = sigmoid_fast(gz + hz);
        float ng = tanh_fast(gn + rg * hn);
        float hnew = (1.f - zg) * ng + zg * hprev;
        hprev = hnew;

        // publish self-flagged pair {hnew, s+1} into buffer (s+1)&1 — no fence, no barrier
        U2 o; o.f.x = hnew; o.f.y = (float)(s + 1);
        st_rlx64(hp2 + (size_t)((s + 1) & 1) * BB * HH + (size_t)fb * HH + gu, o.u);

        // output store off the critical inter-CTA path
        int opos; float oval;
        if (dir == 0){ opos = s; oval = (s < mylen) ? hnew : 0.f; }
        else { if (s < mylen){ opos = mylen - 1 - s; oval = hnew; } else { opos = s; oval = 0.f; } }
        outh[((size_t)fb * T + opos) * DHH + dir * HH + gu] = oval;
    }
}

// ------------------------- scores[b,d,q] = <doc_h[b,d], qry_h[b,q]> -------------------------
__global__ __launch_bounds__(256) void k_scores(){
    __shared__ __align__(16) float As[32][132];
    __shared__ __align__(16) float Bs[32][36];
    int b = blockIdx.y, d0 = blockIdx.x * 128;
    int tid = threadIdx.x;
    int ty = tid >> 4, tx = tid & 15;
    float acc[8][2];
#pragma unroll
    for (int i = 0; i < 8; i++){ acc[i][0] = 0.f; acc[i][1] = 0.f; }

    for (int kc = 0; kc < DHH; kc += 32){
#pragma unroll
        for (int i = 0; i < 4; i++){
            int idx = tid + i * 256;
            int r = idx >> 3, c = (idx & 7) << 2;
            float4 v = *(const float4*)(g_doch + ((size_t)(b*TDD + d0 + r)) * DHH + kc + c);
            As[c+0][r] = v.x; As[c+1][r] = v.y; As[c+2][r] = v.z; As[c+3][r] = v.w;
        }
        {
            int r = tid >> 3, c = (tid & 7) << 2;
            float4 v = *(const float4*)(g_qryh + ((size_t)(b*TQQ + r)) * DHH + kc + c);
            Bs[c+0][r] = v.x; Bs[c+1][r] = v.y; Bs[c+2][r] = v.z; Bs[c+3][r] = v.w;
        }
        __syncthreads();
#pragma unroll
        for (int kk = 0; kk < 32; kk++){
            float4 a0 = *(const float4*)&As[kk][ty*8];
            float4 a1 = *(const float4*)&As[kk][ty*8+4];
            float2 bq = *(const float2*)&Bs[kk][tx*2];
            float a[8] = {a0.x,a0.y,a0.z,a0.w,a1.x,a1.y,a1.z,a1.w};
#pragma unroll
            for (int i = 0; i < 8; i++){ acc[i][0] += a[i]*bq.x; acc[i][1] += a[i]*bq.y; }
        }
        __syncthreads();
    }
#pragma unroll
    for (int i = 0; i < 8; i++){
        float2 o = make_float2(acc[i][0], acc[i][1]);
        *(float2*)(g_scores + ((size_t)(b*TDD + d0 + ty*8 + i)) * TQQ + tx*2) = o;
    }
}

// ------------------------- column (axis=d) max & masked exp-sum -------------------------
__global__ __launch_bounds__(256) void k_col(const int* __restrict__ dlens, const int* __restrict__ qlens){
    int b = blockIdx.x, t = threadIdx.x;
    int q = t & 31, ds = t >> 5;
    int dlen = dlens[b], qlen = qlens[b];
    __shared__ float red1[8][32];
    __shared__ float cm_s[32];
    const float* sc = g_scores + (size_t)b * TDD * TQQ;

    float lm = -1e30f;
    for (int j = 0; j < 128; j++){ int d = ds*128 + j; lm = fmaxf(lm, sc[d*TQQ + q]); }
    red1[ds][q] = lm; __syncthreads();
    if (t < 32){
        float m = red1[0][t];
#pragma unroll
        for (int k = 1; k < 8; k++) m = fmaxf(m, red1[k][t]);
        cm_s[t] = m; g_colmax[b*TQQ + t] = m;
    }
    __syncthreads();
    float cm = cm_s[q];
    float ls = 0.f;
    if (q < qlen)
        for (int j = 0; j < 128; j++){ int d = ds*128 + j; if (d < dlen) ls += expf(sc[d*TQQ + q] - cm); }
    __syncthreads();
    red1[ds][q] = ls; __syncthreads();
    if (t < 32){
        float ssum = 0.f;
#pragma unroll
        for (int k = 0; k < 8; k++) ssum += red1[k][t];
        g_colsum[b*TQQ + t] = ssum;
    }
}

// ------------------------- beta (softmax over q) column-summed -------------------------
__global__ __launch_bounds__(256) void k_beta(const int* __restrict__ dlens, const int* __restrict__ qlens){
    int b = blockIdx.x, w = threadIdx.x >> 5, q = threadIdx.x & 31;
    int dlen = dlens[b], qlen = qlens[b];
    const float* sc = g_scores + (size_t)b * TDD * TQQ;
    float bacc = 0.f;
    for (int i = 0; i < 128; i++){
        int d = i*8 + w;
        if (d < dlen){
            float v = sc[d*TQQ + q];
            float rm = wmax(v);                    // unmasked row max (matches reference)
            float e = (q < qlen) ? expf(v - rm) : 0.f;
            float rs = wsum(e);
            bacc += e / (rs + EPSF);
        }
    }
    atomicAdd(&g_betasum[b*TQQ + q], bacc);
}

// ------------------------- w[b,q] = (betasum/dlen) / (colsum + eps) -------------------------
__global__ __launch_bounds__(256) void k_w(const int* __restrict__ dlens){
    int t = blockIdx.x * 256 + threadIdx.x;   // 8x256 = 2048
    int b = t >> 5;
    g_wq[t] = (g_betasum[t] / (float)dlens[b]) / (g_colsum[t] + EPSF);
}

// ------------------------- s[b,d] -> probs + vocab segment sums -------------------------
__global__ __launch_bounds__(256) void k_s(const int* __restrict__ docs, const int* __restrict__ dlens,
                                           const int* __restrict__ ans, float* __restrict__ out){
    int b = blockIdx.x, w = threadIdx.x >> 5, q = threadIdx.x & 31;
    __shared__ float cm_s[32], w_s[32];
    if (threadIdx.x < 32){ cm_s[threadIdx.x] = g_colmax[b*TQQ + threadIdx.x]; w_s[threadIdx.x] = g_wq[b*TQQ + threadIdx.x]; }
    __syncthreads();
    int dlen = dlens[b], a = ans[b];
    const float* sc = g_scores + (size_t)b * TDD * TQQ;
    const int* db = docs + b * TDD;
    float* sums = g_sums + (size_t)b * VV;
    float cm = cm_s[q], wq = w_s[q];
    for (int i = 0; i < 128; i++){
        int d = i*8 + w;
        if (d < dlen){
            float e = expf(sc[d*TQQ + q] - cm) * wq;   // wq==0 at invalid q
            float sv = wsum(e);
            if (q == 0){
                int tok = db[d];
                atomicAdd(&sums[tok], sv);
                if (tok == a) atomicAdd(&out[b], sv);
            }
        }
    }
}

// ------------------------- argmax over word scores (tie -> smallest vocab id) -------------------------
__global__ __launch_bounds__(256) void k_argmax(const int* __restrict__ docs, const int* __restrict__ dlens){
    int i = blockIdx.x * 256 + threadIdx.x;    // 65536
    int b = i >> 10, d = i & 1023;
    if (d < dlens[b]){
        int tok = docs[i];
        float f = g_sums[(size_t)b * VV + tok];           // f >= 0 -> bits monotone
        unsigned long long key = ((unsigned long long)__float_as_uint(f) << 32) | (unsigned)(VV - 1 - tok);
        atomicMax(&g_key[b], key);
    }
}

__global__ void k_final(float* __restrict__ out){
    int b = threadIdx.x;
    if (b < BB) out[BB + b] = (float)(VV - 1 - (unsigned)(g_key[b] & 0xffffffffull));
}

// ------------------------- launcher -------------------------
extern "C" void kernel_launch(void* const* d_in, const int* in_sizes, int n_in,
                              void* d_out, int out_size){
    const int*   docs  = (const int*)d_in[0];
    const int*   dlens = (const int*)d_in[1];
    const int*   qrys  = (const int*)d_in[2];
    const int*   qlens = (const int*)d_in[3];
    const int*   ans   = (const int*)d_in[4];
    const float* emb   = (const float*)d_in[5];
    const float* Wih_f = (const float*)d_in[6];
    const float* Whh_f = (const float*)d_in[7];
    const float* bih_f = (const float*)d_in[8];
    const float* bhh_f = (const float*)d_in[9];
    const float* Wih_b = (const float*)d_in[10];
    const float* Whh_b = (const float*)d_in[11];
    const float* bih_b = (const float*)d_in[12];
    const float* bhh_b = (const float*)d_in[13];
    float* out = (float*)d_out;

    k_reset<<<256, 256>>>(docs, out);                                               // 0
    k_xw<<<dim3(512, 12), 256>>>(docs, 1, dlens, emb, Wih_f, Wih_b, bih_f, bih_b);  // 1
    k_xw<<<dim3(16,  12), 256>>>(qrys, 0, qlens, emb, Wih_f, Wih_b, bih_f, bih_b);  // 2
    k_rnn<<<128, 256>>>(1, TDD, Whh_f, bhh_f, Whh_b, bhh_b, dlens);                 // 3  <- profiled
    k_rnn<<<128, 256>>>(0, TQQ, Whh_f, bhh_f, Whh_b, bhh_b, qlens);                 // 4
    k_scores<<<dim3(TDD/128, BB), 256>>>();
    k_col<<<BB, 256>>>(dlens, qlens);
    k_beta<<<BB, 256>>>(dlens, qlens);
    k_w<<<8, 256>>>(dlens);
    k_s<<<BB, 256>>>(docs, dlens, ans, out);
    k_argmax<<<256, 256>>>(docs, dlens);
    k_final<<<1, 64>>>(out);
}

// round 15
// speedup vs baseline: 1.0979x; 1.0979x over previous
#include <cuda_runtime.h>
#include <math.h>

#define BB   64
#define TDD  1024
#define TQQ  32
#define EE   384
#define HH   256
#define GG   1536   // 2 dirs x 3H
#define DHH  512
#define VV   50000
#define EPSF 1e-12f

// ------------------------- device scratch (no allocations) -------------------------
__device__ float g_xw  [(size_t)BB*TDD*GG];   // doc xw, fwd[0,768) bwd[768,1536)
__device__ float g_xwq [(size_t)BB*TQQ*GG];   // qry xw
__device__ float g_doch[(size_t)BB*TDD*DHH];  // doc hidden (fwd|bwd), masked-zero
__device__ float g_qryh[(size_t)BB*TQQ*DHH];  // qry hidden, masked-zero
__device__ float g_hdoc[2*2*BB*HH];           // [dir][parity][b][h]
__device__ float g_hqry[2*2*BB*HH];
__device__ float g_scores[(size_t)BB*TDD*TQQ];
__device__ float g_colmax[BB*TQQ];
__device__ float g_wq[BB*TQQ];
__device__ float g_sums[(size_t)BB*VV];
__device__ unsigned g_seq[32*256];            // 32 groups x 8 producers x 32-word stride
__device__ unsigned long long g_key[BB];

// ------------------------- packed f32x2 helpers -------------------------
union U2 { unsigned long long u; float2 f; };

__device__ __forceinline__ void fma2(unsigned long long &d, unsigned long long a, unsigned long long b){
    asm("fma.rn.f32x2 %0, %1, %2, %0;" : "+l"(d) : "l"(a), "l"(b));
}
__device__ __forceinline__ unsigned long long dup2(float x){
    U2 t; t.f.x = x; t.f.y = x; return t.u;
}
__device__ __forceinline__ unsigned long long pk2(float x, float y){
    U2 t; t.f.x = x; t.f.y = y; return t.u;
}

// ------------------------- acquire/release flag helpers -------------------------
__device__ __forceinline__ unsigned ld_acq(const unsigned* p){
    unsigned v;
    asm volatile("ld.acquire.gpu.global.u32 %0, [%1];" : "=r"(v) : "l"(p) : "memory");
    return v;
}
__device__ __forceinline__ void st_rel(unsigned* p, unsigned v){
    asm volatile("st.release.gpu.global.u32 [%0], %1;" :: "l"(p), "r"(v) : "memory");
}

// ------------------------- misc warp helpers -------------------------
__device__ __forceinline__ float wsum(float v){
#pragma unroll
    for (int o = 16; o; o >>= 1) v += __shfl_xor_sync(0xffffffffu, v, o);
    return v;
}
__device__ __forceinline__ float wmax(float v){
#pragma unroll
    for (int o = 16; o; o >>= 1) v = fmaxf(v, __shfl_xor_sync(0xffffffffu, v, o));
    return v;
}

// ------------------------- reset -------------------------
__global__ __launch_bounds__(256) void k_reset(const int* __restrict__ docs, float* __restrict__ out){
    int i = blockIdx.x * 256 + threadIdx.x;               // grid 256x256 = 65536
    g_hdoc[i] = 0.f;                                      // 2*2*64*256 = 65536
    g_hqry[i] = 0.f;
    if (i < 32*256) g_seq[i] = 0u;
    if (i < 128)  out[i] = 0.f;
    if (i < 64)   g_key[i] = 0ull;
    int b = i >> 10;                                      // scatter-zero touched vocab slots
    g_sums[(size_t)b * VV + docs[i]] = 0.f;
}

// ------------------------- xw GEMM: gather(emb) @ [Wf;Wb]^T + bias -------------------------
// 128x128 tile, 256 threads, 8x8 microtile on fma.rn.f32x2 (pairs over M).
__global__ __launch_bounds__(256) void k_xw(const int* __restrict__ toks, int isdoc,
                                            const int* __restrict__ lens,
                                            const float* __restrict__ emb,
                                            const float* __restrict__ Wf, const float* __restrict__ Wb,
                                            const float* __restrict__ bf, const float* __restrict__ bb){
    __shared__ __align__(16) float As[32][132];   // [k][m]
    __shared__ __align__(16) float Ws[32][132];   // [k][n]
    __shared__ int tk[128];
    float* outp = isdoc ? g_xw : g_xwq;
    int tid = threadIdx.x;
    int m0 = blockIdx.x * 128, n0 = blockIdx.y * 128;
    if (isdoc){
        int b = m0 >> 10;
        if ((m0 & 1023) >= lens[b]) return;       // tile fully beyond doc len: rows stay 0, never read
    }
    const float* W; const float* bias;
    if (n0 < 768){ W = Wf + (size_t)n0 * EE;        bias = bf + n0; }
    else         { W = Wb + (size_t)(n0-768) * EE;  bias = bb + (n0-768); }
    if (tid < 128) tk[tid] = toks[m0 + tid];
    __syncthreads();

    int ty = tid >> 4, tx = tid & 15;             // rows ty*8..+7, cols tx*8..+7
    int rr = tid & 127, kq0 = tid >> 7;           // fill: kq = kq0 + 2*i, i<4
    const float* arow = emb + (size_t)tk[rr] * EE;
    const float* wrow = W   + (size_t)rr * EE;

    U2 acc[4][8];                                 // [M-pair][N]
#pragma unroll
    for (int i = 0; i < 4; i++)
#pragma unroll
        for (int j = 0; j < 8; j++) acc[i][j].f = make_float2(0.f, 0.f);

    float4 ra[4], rw[4];
#pragma unroll
    for (int i = 0; i < 4; i++){
        ra[i] = *(const float4*)(arow + (kq0 + 2*i)*4);
        rw[i] = *(const float4*)(wrow + (kq0 + 2*i)*4);
    }

    for (int c = 0; c < 12; c++){
        __syncthreads();
#pragma unroll
        for (int i = 0; i < 4; i++){
            int kb = (kq0 + 2*i) * 4;
            As[kb+0][rr] = ra[i].x; As[kb+1][rr] = ra[i].y; As[kb+2][rr] = ra[i].z; As[kb+3][rr] = ra[i].w;
            Ws[kb+0][rr] = rw[i].x; Ws[kb+1][rr] = rw[i].y; Ws[kb+2][rr] = rw[i].z; Ws[kb+3][rr] = rw[i].w;
        }
        __syncthreads();
        if (c + 1 < 12){
            int kt = (c + 1) * 32;
#pragma unroll
            for (int i = 0; i < 4; i++){
                ra[i] = *(const float4*)(arow + kt + (kq0 + 2*i)*4);
                rw[i] = *(const float4*)(wrow + kt + (kq0 + 2*i)*4);
            }
        }
#pragma unroll 4
        for (int kk = 0; kk < 32; kk++){
            float4 a0 = *(const float4*)&As[kk][ty*8];
            float4 a1 = *(const float4*)&As[kk][ty*8 + 4];
            float4 w0 = *(const float4*)&Ws[kk][tx*8];
            float4 w1 = *(const float4*)&Ws[kk][tx*8 + 4];
            unsigned long long ap[4] = { pk2(a0.x, a0.y), pk2(a0.z, a0.w),
                                         pk2(a1.x, a1.y), pk2(a1.z, a1.w) };
            unsigned long long wd[8] = { dup2(w0.x), dup2(w0.y), dup2(w0.z), dup2(w0.w),
                                         dup2(w1.x), dup2(w1.y), dup2(w1.z), dup2(w1.w) };
#pragma unroll
            for (int ip = 0; ip < 4; ip++)
#pragma unroll
                for (int j = 0; j < 8; j++) fma2(acc[ip][j].u, ap[ip], wd[j]);
        }
    }

    float4 bv0 = *(const float4*)(bias + tx*8);
    float4 bv1 = *(const float4*)(bias + tx*8 + 4);
    float bb8[8] = {bv0.x, bv0.y, bv0.z, bv0.w, bv1.x, bv1.y, bv1.z, bv1.w};
#pragma unroll
    for (int ip = 0; ip < 4; ip++){
        size_t r0 = (size_t)m0 + ty*8 + 2*ip;
        float4 o0 = make_float4(acc[ip][0].f.x + bb8[0], acc[ip][1].f.x + bb8[1],
                                acc[ip][2].f.x + bb8[2], acc[ip][3].f.x + bb8[3]);
        float4 o1 = make_float4(acc[ip][4].f.x + bb8[4], acc[ip][5].f.x + bb8[5],
                                acc[ip][6].f.x + bb8[6], acc[ip][7].f.x + bb8[7]);
        float4 o2 = make_float4(acc[ip][0].f.y + bb8[0], acc[ip][1].f.y + bb8[1],
                                acc[ip][2].f.y + bb8[2], acc[ip][3].f.y + bb8[3]);
        float4 o3 = make_float4(acc[ip][4].f.y + bb8[4], acc[ip][5].f.y + bb8[5],
                                acc[ip][6].f.y + bb8[6], acc[ip][7].f.y + bb8[7]);
        *(float4*)(outp + r0 * GG + n0 + tx*8)           = o0;
        *(float4*)(outp + r0 * GG + n0 + tx*8 + 4)       = o1;
        *(float4*)(outp + (r0 + 1) * GG + n0 + tx*8)     = o2;
        *(float4*)(outp + (r0 + 1) * GG + n0 + tx*8 + 4) = o3;
    }
}

// ------------------------- persistent bidirectional GRU recurrence -------------------------
// R12 protocol (per-producer seq words, release/acquire) + batch-skip: partial blocks for
// batches with s >= len are skipped (warp-uniform; garbage h stays confined to dead batches,
// whose outputs are explicitly masked).
__global__ __launch_bounds__(256,1) void k_rnn(int isdoc, int T,
                                               const float* __restrict__ Whh_f, const float* __restrict__ bhh_f,
                                               const float* __restrict__ Whh_b, const float* __restrict__ bhh_b,
                                               const int* __restrict__ lens){
    int dir = blockIdx.x >> 6;
    int rem = blockIdx.x & 63;
    int bs  = rem >> 3;
    int js  = rem & 7;
    int tid = threadIdx.x;
    int u   = tid & 31;      // unit lane
    int ks  = tid >> 5;      // k-slice (compute role) == batch (finalize role)
    int b0  = bs * 8;
    int gu  = js * 32 + u;

    const float* xw  = isdoc ? g_xw   : g_xwq;
    float*       outh= isdoc ? g_doch : g_qryh;
    float*       hb  = (isdoc ? g_hdoc : g_hqry) + (size_t)dir * 2 * BB * HH;
    const float* Whh = dir ? Whh_b : Whh_f;
    const float* bhh = dir ? bhh_b : bhh_f;
    unsigned* seq = &g_seq[((isdoc ? 0 : 16) + dir * 8 + bs) * 256];   // 8 producers, 32-word stride

    U2 w0p[16], w1p[16], w2p[16];
#pragma unroll
    for (int kk = 0; kk < 16; kk++){
        w0p[kk].f = *(const float2*)&Whh[(size_t)(gu)        * HH + ks*32 + kk*2];
        w1p[kk].f = *(const float2*)&Whh[(size_t)(HH + gu)   * HH + ks*32 + kk*2];
        w2p[kk].f = *(const float2*)&Whh[(size_t)(2*HH + gu) * HH + ks*32 + kk*2];
    }
    float bh0 = bhh[gu], bh1 = bhh[HH+gu], bh2 = bhh[2*HH+gu];
    int fb = b0 + ks;                     // finalize batch
    int mylen = lens[fb];
    int glen[8];
    int Tgrp = 0;
#pragma unroll
    for (int i = 0; i < 8; i++){ glen[i] = lens[b0 + i]; Tgrp = (glen[i] > Tgrp) ? glen[i] : Tgrp; }

    __shared__ __align__(16) float h_s[8][HH];
    __shared__ float red[8][3][8][32];    // [kslice][row][batch][unit]

    for (int s = 0; s < Tgrp; s++){
        // prefetch xw for this step (in flight across the wait)
        int xpos = dir ? ((s < mylen) ? (mylen - 1 - s) : 0) : s;
        const float* xp = xw + ((size_t)fb * T + xpos) * GG + dir * 768;
        float gr = __ldg(xp + gu);
        float gz = __ldg(xp + 256 + gu);
        float gn = __ldg(xp + 512 + gu);

        int p = s & 1;
        if (s > 0){
            if (tid < 8){ while (ld_acq(&seq[tid * 32]) < (unsigned)s) { } }
            __syncthreads();              // acquire by tid0-7 propagated CTA-wide
        }
        // stage h (8 batches x 256 = 512 float4) from the global double buffer, L2-only
        {
            const float4* src = (const float4*)(hb + (size_t)p * BB * HH + (size_t)b0 * HH);
            float4* dst = (float4*)h_s;
            dst[tid]       = __ldcg(src + tid);
            dst[tid + 256] = __ldcg(src + tid + 256);
        }
        __syncthreads();

        // partial dot products: this thread's 32-k slice, ACTIVE batches only, 3 gate rows (f32x2)
#pragma unroll
        for (int bl = 0; bl < 8; bl++){
            if (s < glen[bl]){                       // warp-uniform skip of dead batches
                const float4* hp = (const float4*)&h_s[bl][ks*32];
                U2 A0, A1, A2;
                A0.f = make_float2(0.f,0.f); A1.f = make_float2(0.f,0.f); A2.f = make_float2(0.f,0.f);
#pragma unroll
                for (int k4 = 0; k4 < 8; k4++){
                    float4 hv = hp[k4];
                    unsigned long long p0 = pk2(hv.x, hv.y);
                    unsigned long long p1 = pk2(hv.z, hv.w);
                    fma2(A0.u, p0, w0p[2*k4].u); fma2(A0.u, p1, w0p[2*k4+1].u);
                    fma2(A1.u, p0, w1p[2*k4].u); fma2(A1.u, p1, w1p[2*k4+1].u);
                    fma2(A2.u, p0, w2p[2*k4].u); fma2(A2.u, p1, w2p[2*k4+1].u);
                }
                red[ks][0][bl][u] = A0.f.x + A0.f.y;
                red[ks][1][bl][u] = A1.f.x + A1.f.y;
                red[ks][2][bl][u] = A2.f.x + A2.f.y;
            }
        }
        __syncthreads();

        // finalize: thread handles (batch=fb, unit=gu); dead batches produce garbage that
        // only feeds themselves and is masked at output
        float hr = bh0, hz = bh1, hn = bh2;
#pragma unroll
        for (int k = 0; k < 8; k++){
            hr += red[k][0][ks][u]; hz += red[k][1][ks][u]; hn += red[k][2][ks][u];
        }
        float rg = 1.f / (1.f + expf(-(gr + hr)));
        float zg = 1.f / (1.f + expf(-(gz + hz)));
        float ng = tanhf(gn + rg * hn);
        float hprev = h_s[ks][gu];
        float hnew = (1.f - zg) * ng + zg * hprev;
        __stcg(&hb[(size_t)(p ^ 1) * BB * HH + (size_t)fb * HH + gu], hnew);

        __syncthreads();                  // CTA-scope: all h stores ordered before the release
        if (tid == 0) st_rel(&seq[js * 32], (unsigned)(s + 1));

        // output store off the critical inter-CTA path
        int opos; float oval;
        if (dir == 0){ opos = s; oval = (s < mylen) ? hnew : 0.f; }
        else { if (s < mylen){ opos = mylen - 1 - s; oval = hnew; } else { opos = s; oval = 0.f; } }
        outh[((size_t)fb * T + opos) * DHH + dir * HH + gu] = oval;
    }
}

// ------------------------- scores[b,d,q] = <doc_h[b,d], qry_h[b,q]> (f32x2) -------------------------
__global__ __launch_bounds__(256) void k_scores(){
    __shared__ __align__(16) float As[32][132];
    __shared__ __align__(16) float Bs[32][36];
    int b = blockIdx.y, d0 = blockIdx.x * 128;
    int tid = threadIdx.x;
    int ty = tid >> 4, tx = tid & 15;
    U2 acc2[4][2];                               // [row-pair][qcol]
#pragma unroll
    for (int i = 0; i < 4; i++){ acc2[i][0].f = make_float2(0.f,0.f); acc2[i][1].f = make_float2(0.f,0.f); }

    for (int kc = 0; kc < DHH; kc += 32){
#pragma unroll
        for (int i = 0; i < 4; i++){
            int idx = tid + i * 256;
            int r = idx >> 3, c = (idx & 7) << 2;
            float4 v = *(const float4*)(g_doch + ((size_t)(b*TDD + d0 + r)) * DHH + kc + c);
            As[c+0][r] = v.x; As[c+1][r] = v.y; As[c+2][r] = v.z; As[c+3][r] = v.w;
        }
        {
            int r = tid >> 3, c = (tid & 7) << 2;
            float4 v = *(const float4*)(g_qryh + ((size_t)(b*TQQ + r)) * DHH + kc + c);
            Bs[c+0][r] = v.x; Bs[c+1][r] = v.y; Bs[c+2][r] = v.z; Bs[c+3][r] = v.w;
        }
        __syncthreads();
#pragma unroll
        for (int kk = 0; kk < 32; kk++){
            ulonglong2 A01 = *(const ulonglong2*)&As[kk][ty*8];
            ulonglong2 A23 = *(const ulonglong2*)&As[kk][ty*8 + 4];
            float2 bq = *(const float2*)&Bs[kk][tx*2];
            unsigned long long q0 = dup2(bq.x), q1 = dup2(bq.y);
            unsigned long long ap[4] = { A01.x, A01.y, A23.x, A23.y };
#pragma unroll
            for (int ip = 0; ip < 4; ip++){
                fma2(acc2[ip][0].u, ap[ip], q0);
                fma2(acc2[ip][1].u, ap[ip], q1);
            }
        }
        __syncthreads();
    }
#pragma unroll
    for (int ip = 0; ip < 4; ip++){
        size_t r0 = (size_t)(b*TDD + d0 + ty*8 + 2*ip);
        *(float2*)(g_scores + r0 * TQQ + tx*2)       = make_float2(acc2[ip][0].f.x, acc2[ip][1].f.x);
        *(float2*)(g_scores + (r0+1) * TQQ + tx*2)   = make_float2(acc2[ip][0].f.y, acc2[ip][1].f.y);
    }
}

// ------------------------- fused: column max/sum + beta column-sums + w -------------------------
__global__ __launch_bounds__(256) void k_colbetaw(const int* __restrict__ dlens, const int* __restrict__ qlens){
    int b = blockIdx.x, t = threadIdx.x;
    int q = t & 31, w = t >> 5;
    int dlen = dlens[b], qlen = qlens[b];
    __shared__ float redm[8][32], redc[8][32], redb[8][32];
    __shared__ float cm_s[32];
    const float* sc = g_scores + (size_t)b * TDD * TQQ;

    // pass 1: column (axis-d) max, unmasked (invalid entries are exact 0, matching reference)
    float lm = -1e30f;
    for (int j = 0; j < 128; j++){ int d = j*8 + w; lm = fmaxf(lm, sc[d*TQQ + q]); }
    redm[w][q] = lm; __syncthreads();
    if (t < 32){
        float m = redm[0][t];
#pragma unroll
        for (int k = 1; k < 8; k++) m = fmaxf(m, redm[k][t]);
        cm_s[t] = m; g_colmax[b*TQQ + t] = m;
    }
    __syncthreads();
    float cm = cm_s[q];

    // pass 2: per valid d-row: colsum contribution + beta (softmax over q) column-sum
    float csum = 0.f, bacc = 0.f;
    for (int j = 0; j < 128; j++){
        int d = j*8 + w;
        if (d < dlen){
            float v = sc[d*TQQ + q];
            float rm = wmax(v);                    // unmasked row max (matches reference)
            float e = (q < qlen) ? expf(v - rm) : 0.f;
            float rs = wsum(e);
            bacc += e / (rs + EPSF);
            csum += (q < qlen) ? expf(v - cm) : 0.f;
        }
    }
    redc[w][q] = csum; redb[w][q] = bacc; __syncthreads();
    if (t < 32){
        float cs = 0.f, bsum = 0.f;
#pragma unroll
        for (int k = 0; k < 8; k++){ cs += redc[k][t]; bsum += redb[k][t]; }
        g_wq[b*TQQ + t] = (bsum / (float)dlen) / (cs + EPSF);
    }
}

// ------------------------- s[b,d] -> probs + vocab segment sums -------------------------
__global__ __launch_bounds__(256) void k_s(const int* __restrict__ docs, const int* __restrict__ dlens,
                                           const int* __restrict__ ans, float* __restrict__ out){
    int b = blockIdx.x, w = threadIdx.x >> 5, q = threadIdx.x & 31;
    __shared__ float cm_s[32], w_s[32];
    if (threadIdx.x < 32){ cm_s[threadIdx.x] = g_colmax[b*TQQ + threadIdx.x]; w_s[threadIdx.x] = g_wq[b*TQQ + threadIdx.x]; }
    __syncthreads();
    int dlen = dlens[b], a = ans[b];
    const float* sc = g_scores + (size_t)b * TDD * TQQ;
    const int* db = docs + b * TDD;
    float* sums = g_sums + (size_t)b * VV;
    float cm = cm_s[q], wq = w_s[q];
    for (int i = 0; i < 128; i++){
        int d = i*8 + w;
        if (d < dlen){
            float e = expf(sc[d*TQQ + q] - cm) * wq;   // wq==0 at invalid q
            float sv = wsum(e);
            if (q == 0){
                int tok = db[d];
                atomicAdd(&sums[tok], sv);
                if (tok == a) atomicAdd(&out[b], sv);
            }
        }
    }
}

// ------------------------- argmax over word scores (tie -> smallest vocab id) -------------------------
__global__ __launch_bounds__(256) void k_argmax(const int* __restrict__ docs, const int* __restrict__ dlens){
    int i = blockIdx.x * 256 + threadIdx.x;    // 65536
    int b = i >> 10, d = i & 1023;
    if (d < dlens[b]){
        int tok = docs[i];
        float f = g_sums[(size_t)b * VV + tok];           // f >= 0 -> bits monotone
        unsigned long long key = ((unsigned long long)__float_as_uint(f) << 32) | (unsigned)(VV - 1 - tok);
        atomicMax(&g_key[b], key);
    }
}

__global__ void k_final(float* __restrict__ out){
    int b = threadIdx.x;
    if (b < BB) out[BB + b] = (float)(VV - 1 - (unsigned)(g_key[b] & 0xffffffffull));
}

// ------------------------- launcher -------------------------
extern "C" void kernel_launch(void* const* d_in, const int* in_sizes, int n_in,
                              void* d_out, int out_size){
    const int*   docs  = (const int*)d_in[0];
    const int*   dlens = (const int*)d_in[1];
    const int*   qrys  = (const int*)d_in[2];
    const int*   qlens = (const int*)d_in[3];
    const int*   ans   = (const int*)d_in[4];
    const float* emb   = (const float*)d_in[5];
    const float* Wih_f = (const float*)d_in[6];
    const float* Whh_f = (const float*)d_in[7];
    const float* bih_f = (const float*)d_in[8];
    const float* bhh_f = (const float*)d_in[9];
    const float* Wih_b = (const float*)d_in[10];
    const float* Whh_b = (const float*)d_in[11];
    const float* bih_b = (const float*)d_in[12];
    const float* bhh_b = (const float*)d_in[13];
    float* out = (float*)d_out;

    k_reset<<<256, 256>>>(docs, out);                                               // 0
    k_xw<<<dim3(512, 12), 256>>>(docs, 1, dlens, emb, Wih_f, Wih_b, bih_f, bih_b);  // 1
    k_xw<<<dim3(16,  12), 256>>>(qrys, 0, qlens, emb, Wih_f, Wih_b, bih_f, bih_b);  // 2
    k_rnn<<<128, 256>>>(1, TDD, Whh_f, bhh_f, Whh_b, bhh_b, dlens);                 // 3  <- profiled
    k_rnn<<<128, 256>>>(0, TQQ, Whh_f, bhh_f, Whh_b, bhh_b, qlens);                 // 4
    k_scores<<<dim3(TDD/128, BB), 256>>>();
    k_colbetaw<<<BB, 256>>>(dlens, qlens);
    k_s<<<BB, 256>>>(docs, dlens, ans, out);
    k_argmax<<<256, 256>>>(docs, dlens);
    k_final<<<1, 64>>>(out);
}

// round 17
// speedup vs baseline: 1.0987x; 1.0007x over previous
#include <cuda_runtime.h>
#include <math.h>

#define BB   64
#define TDD  1024
#define TQQ  32
#define EE   384
#define HH   256
#define GG   1536   // 2 dirs x 3H
#define DHH  512
#define VV   50000
#define EPSF 1e-12f

// ------------------------- device scratch (no allocations) -------------------------
__device__ float g_xw  [(size_t)BB*TDD*GG];   // doc xw, fwd[0,768) bwd[768,1536)
__device__ float g_xwq [(size_t)BB*TQQ*GG];   // qry xw
__device__ float g_doch[(size_t)BB*TDD*DHH];  // doc hidden (fwd|bwd), masked-zero
__device__ float g_qryh[(size_t)BB*TQQ*DHH];  // qry hidden, masked-zero
__device__ float g_hdoc[2*2*BB*HH];           // [dir][parity][b][h]
__device__ float g_hqry[2*2*BB*HH];
__device__ float g_scores[(size_t)BB*TDD*TQQ];
__device__ float g_colmax[BB*TQQ];
__device__ float g_wq[BB*TQQ];
__device__ float g_sums[(size_t)BB*VV];
__device__ unsigned g_seq[32*256];            // 32 groups x 8 producers x 32-word stride

// ------------------------- packed f32x2 helpers -------------------------
union U2 { unsigned long long u; float2 f; };

__device__ __forceinline__ void fma2(unsigned long long &d, unsigned long long a, unsigned long long b){
    asm("fma.rn.f32x2 %0, %1, %2, %0;" : "+l"(d) : "l"(a), "l"(b));
}
__device__ __forceinline__ unsigned long long dup2(float x){
    U2 t; t.f.x = x; t.f.y = x; return t.u;
}
__device__ __forceinline__ unsigned long long pk2(float x, float y){
    U2 t; t.f.x = x; t.f.y = y; return t.u;
}

// ------------------------- acquire/release flag helpers -------------------------
__device__ __forceinline__ unsigned ld_acq(const unsigned* p){
    unsigned v;
    asm volatile("ld.acquire.gpu.global.u32 %0, [%1];" : "=r"(v) : "l"(p) : "memory");
    return v;
}
__device__ __forceinline__ void st_rel(unsigned* p, unsigned v){
    asm volatile("st.release.gpu.global.u32 [%0], %1;" :: "l"(p), "r"(v) : "memory");
}

// ------------------------- misc warp helpers -------------------------
__device__ __forceinline__ float wsum(float v){
#pragma unroll
    for (int o = 16; o; o >>= 1) v += __shfl_xor_sync(0xffffffffu, v, o);
    return v;
}
__device__ __forceinline__ float wmax(float v){
#pragma unroll
    for (int o = 16; o; o >>= 1) v = fmaxf(v, __shfl_xor_sync(0xffffffffu, v, o));
    return v;
}

// ------------------------- reset -------------------------
__global__ __launch_bounds__(256) void k_reset(const int* __restrict__ docs, float* __restrict__ out){
    int i = blockIdx.x * 256 + threadIdx.x;               // grid 256x256 = 65536
    g_hdoc[i] = 0.f;                                      // 2*2*64*256 = 65536
    g_hqry[i] = 0.f;
    if (i < 32*256) g_seq[i] = 0u;
    if (i < 128)  out[i] = 0.f;
    int b = i >> 10;                                      // scatter-zero touched vocab slots
    g_sums[(size_t)b * VV + docs[i]] = 0.f;
}

// ------------------------- xw GEMM: gather(emb) @ [Wf;Wb]^T + bias -------------------------
// 128x128 tile, 256 threads, 8x8 microtile on fma.rn.f32x2 (pairs over M).
__global__ __launch_bounds__(256) void k_xw(const int* __restrict__ toks, int isdoc,
                                            const int* __restrict__ lens,
                                            const float* __restrict__ emb,
                                            const float* __restrict__ Wf, const float* __restrict__ Wb,
                                            const float* __restrict__ bf, const float* __restrict__ bb){
    __shared__ __align__(16) float As[32][132];   // [k][m]
    __shared__ __align__(16) float Ws[32][132];   // [k][n]
    __shared__ int tk[128];
    float* outp = isdoc ? g_xw : g_xwq;
    int tid = threadIdx.x;
    int m0 = blockIdx.x * 128, n0 = blockIdx.y * 128;
    if (isdoc){
        int b = m0 >> 10;
        if ((m0 & 1023) >= lens[b]) return;       // tile fully beyond doc len: rows stay 0, never read
    }
    const float* W; const float* bias;
    if (n0 < 768){ W = Wf + (size_t)n0 * EE;        bias = bf + n0; }
    else         { W = Wb + (size_t)(n0-768) * EE;  bias = bb + (n0-768); }
    if (tid < 128) tk[tid] = toks[m0 + tid];
    __syncthreads();

    int ty = tid >> 4, tx = tid & 15;             // rows ty*8..+7, cols tx*8..+7
    int rr = tid & 127, kq0 = tid >> 7;           // fill: kq = kq0 + 2*i, i<4
    const float* arow = emb + (size_t)tk[rr] * EE;
    const float* wrow = W   + (size_t)rr * EE;

    U2 acc[4][8];                                 // [M-pair][N]
#pragma unroll
    for (int i = 0; i < 4; i++)
#pragma unroll
        for (int j = 0; j < 8; j++) acc[i][j].f = make_float2(0.f, 0.f);

    float4 ra[4], rw[4];
#pragma unroll
    for (int i = 0; i < 4; i++){
        ra[i] = *(const float4*)(arow + (kq0 + 2*i)*4);
        rw[i] = *(const float4*)(wrow + (kq0 + 2*i)*4);
    }

    for (int c = 0; c < 12; c++){
        __syncthreads();
#pragma unroll
        for (int i = 0; i < 4; i++){
            int kb = (kq0 + 2*i) * 4;
            As[kb+0][rr] = ra[i].x; As[kb+1][rr] = ra[i].y; As[kb+2][rr] = ra[i].z; As[kb+3][rr] = ra[i].w;
            Ws[kb+0][rr] = rw[i].x; Ws[kb+1][rr] = rw[i].y; Ws[kb+2][rr] = rw[i].z; Ws[kb+3][rr] = rw[i].w;
        }
        __syncthreads();
        if (c + 1 < 12){
            int kt = (c + 1) * 32;
#pragma unroll
            for (int i = 0; i < 4; i++){
                ra[i] = *(const float4*)(arow + kt + (kq0 + 2*i)*4);
                rw[i] = *(const float4*)(wrow + kt + (kq0 + 2*i)*4);
            }
        }
#pragma unroll 4
        for (int kk = 0; kk < 32; kk++){
            float4 a0 = *(const float4*)&As[kk][ty*8];
            float4 a1 = *(const float4*)&As[kk][ty*8 + 4];
            float4 w0 = *(const float4*)&Ws[kk][tx*8];
            float4 w1 = *(const float4*)&Ws[kk][tx*8 + 4];
            unsigned long long ap[4] = { pk2(a0.x, a0.y), pk2(a0.z, a0.w),
                                         pk2(a1.x, a1.y), pk2(a1.z, a1.w) };
            unsigned long long wd[8] = { dup2(w0.x), dup2(w0.y), dup2(w0.z), dup2(w0.w),
                                         dup2(w1.x), dup2(w1.y), dup2(w1.z), dup2(w1.w) };
#pragma unroll
            for (int ip = 0; ip < 4; ip++)
#pragma unroll
                for (int j = 0; j < 8; j++) fma2(acc[ip][j].u, ap[ip], wd[j]);
        }
    }

    float4 bv0 = *(const float4*)(bias + tx*8);
    float4 bv1 = *(const float4*)(bias + tx*8 + 4);
    float bb8[8] = {bv0.x, bv0.y, bv0.z, bv0.w, bv1.x, bv1.y, bv1.z, bv1.w};
#pragma unroll
    for (int ip = 0; ip < 4; ip++){
        size_t r0 = (size_t)m0 + ty*8 + 2*ip;
        float4 o0 = make_float4(acc[ip][0].f.x + bb8[0], acc[ip][1].f.x + bb8[1],
                                acc[ip][2].f.x + bb8[2], acc[ip][3].f.x + bb8[3]);
        float4 o1 = make_float4(acc[ip][4].f.x + bb8[4], acc[ip][5].f.x + bb8[5],
                                acc[ip][6].f.x + bb8[6], acc[ip][7].f.x + bb8[7]);
        float4 o2 = make_float4(acc[ip][0].f.y + bb8[0], acc[ip][1].f.y + bb8[1],
                                acc[ip][2].f.y + bb8[2], acc[ip][3].f.y + bb8[3]);
        float4 o3 = make_float4(acc[ip][4].f.y + bb8[4], acc[ip][5].f.y + bb8[5],
                                acc[ip][6].f.y + bb8[6], acc[ip][7].f.y + bb8[7]);
        *(float4*)(outp + r0 * GG + n0 + tx*8)           = o0;
        *(float4*)(outp + r0 * GG + n0 + tx*8 + 4)       = o1;
        *(float4*)(outp + (r0 + 1) * GG + n0 + tx*8)     = o2;
        *(float4*)(outp + (r0 + 1) * GG + n0 + tx*8 + 4) = o3;
    }
}

// ------------------------- persistent bidirectional GRU recurrence -------------------------
// R12 protocol (per-producer seq words, release/acquire) + batch-skip (R15).
__global__ __launch_bounds__(256,1) void k_rnn(int isdoc, int T,
                                               const float* __restrict__ Whh_f, const float* __restrict__ bhh_f,
                                               const float* __restrict__ Whh_b, const float* __restrict__ bhh_b,
                                               const int* __restrict__ lens){
    int dir = blockIdx.x >> 6;
    int rem = blockIdx.x & 63;
    int bs  = rem >> 3;
    int js  = rem & 7;
    int tid = threadIdx.x;
    int u   = tid & 31;
    int ks  = tid >> 5;
    int b0  = bs * 8;
    int gu  = js * 32 + u;

    const float* xw  = isdoc ? g_xw   : g_xwq;
    float*       outh= isdoc ? g_doch : g_qryh;
    float*       hb  = (isdoc ? g_hdoc : g_hqry) + (size_t)dir * 2 * BB * HH;
    const float* Whh = dir ? Whh_b : Whh_f;
    const float* bhh = dir ? bhh_b : bhh_f;
    unsigned* seq = &g_seq[((isdoc ? 0 : 16) + dir * 8 + bs) * 256];

    U2 w0p[16], w1p[16], w2p[16];
#pragma unroll
    for (int kk = 0; kk < 16; kk++){
        w0p[kk].f = *(const float2*)&Whh[(size_t)(gu)        * HH + ks*32 + kk*2];
        w1p[kk].f = *(const float2*)&Whh[(size_t)(HH + gu)   * HH + ks*32 + kk*2];
        w2p[kk].f = *(const float2*)&Whh[(size_t)(2*HH + gu) * HH + ks*32 + kk*2];
    }
    float bh0 = bhh[gu], bh1 = bhh[HH+gu], bh2 = bhh[2*HH+gu];
    int fb = b0 + ks;
    int mylen = lens[fb];
    int glen[8];
    int Tgrp = 0;
#pragma unroll
    for (int i = 0; i < 8; i++){ glen[i] = lens[b0 + i]; Tgrp = (glen[i] > Tgrp) ? glen[i] : Tgrp; }

    __shared__ __align__(16) float h_s[8][HH];
    __shared__ float red[8][3][8][32];

    for (int s = 0; s < Tgrp; s++){
        int xpos = dir ? ((s < mylen) ? (mylen - 1 - s) : 0) : s;
        const float* xp = xw + ((size_t)fb * T + xpos) * GG + dir * 768;
        float gr = __ldg(xp + gu);
        float gz = __ldg(xp + 256 + gu);
        float gn = __ldg(xp + 512 + gu);

        int p = s & 1;
        if (s > 0){
            if (tid < 8){ while (ld_acq(&seq[tid * 32]) < (unsigned)s) { } }
            __syncthreads();
        }
        {
            const float4* src = (const float4*)(hb + (size_t)p * BB * HH + (size_t)b0 * HH);
            float4* dst = (float4*)h_s;
            dst[tid]       = __ldcg(src + tid);
            dst[tid + 256] = __ldcg(src + tid + 256);
        }
        __syncthreads();

#pragma unroll
        for (int bl = 0; bl < 8; bl++){
            if (s < glen[bl]){
                const float4* hp = (const float4*)&h_s[bl][ks*32];
                U2 A0, A1, A2;
                A0.f = make_float2(0.f,0.f); A1.f = make_float2(0.f,0.f); A2.f = make_float2(0.f,0.f);
#pragma unroll
                for (int k4 = 0; k4 < 8; k4++){
                    float4 hv = hp[k4];
                    unsigned long long p0 = pk2(hv.x, hv.y);
                    unsigned long long p1 = pk2(hv.z, hv.w);
                    fma2(A0.u, p0, w0p[2*k4].u); fma2(A0.u, p1, w0p[2*k4+1].u);
                    fma2(A1.u, p0, w1p[2*k4].u); fma2(A1.u, p1, w1p[2*k4+1].u);
                    fma2(A2.u, p0, w2p[2*k4].u); fma2(A2.u, p1, w2p[2*k4+1].u);
                }
                red[ks][0][bl][u] = A0.f.x + A0.f.y;
                red[ks][1][bl][u] = A1.f.x + A1.f.y;
                red[ks][2][bl][u] = A2.f.x + A2.f.y;
            }
        }
        __syncthreads();

        float hr = bh0, hz = bh1, hn = bh2;
#pragma unroll
        for (int k = 0; k < 8; k++){
            hr += red[k][0][ks][u]; hz += red[k][1][ks][u]; hn += red[k][2][ks][u];
        }
        float rg = 1.f / (1.f + expf(-(gr + hr)));
        float zg = 1.f / (1.f + expf(-(gz + hz)));
        float ng = tanhf(gn + rg * hn);
        float hprev = h_s[ks][gu];
        float hnew = (1.f - zg) * ng + zg * hprev;
        __stcg(&hb[(size_t)(p ^ 1) * BB * HH + (size_t)fb * HH + gu], hnew);

        __syncthreads();
        if (tid == 0) st_rel(&seq[js * 32], (unsigned)(s + 1));

        int opos; float oval;
        if (dir == 0){ opos = s; oval = (s < mylen) ? hnew : 0.f; }
        else { if (s < mylen){ opos = mylen - 1 - s; oval = hnew; } else { opos = s; oval = 0.f; } }
        outh[((size_t)fb * T + opos) * DHH + dir * HH + gu] = oval;
    }
}

// ------------------------- scores[b,d,q] = <doc_h[b,d], qry_h[b,q]> (f32x2) -------------------------
__global__ __launch_bounds__(256) void k_scores(){
    __shared__ __align__(16) float As[32][132];
    __shared__ __align__(16) float Bs[32][36];
    int b = blockIdx.y, d0 = blockIdx.x * 128;
    int tid = threadIdx.x;
    int ty = tid >> 4, tx = tid & 15;
    U2 acc2[4][2];
#pragma unroll
    for (int i = 0; i < 4; i++){ acc2[i][0].f = make_float2(0.f,0.f); acc2[i][1].f = make_float2(0.f,0.f); }

    for (int kc = 0; kc < DHH; kc += 32){
#pragma unroll
        for (int i = 0; i < 4; i++){
            int idx = tid + i * 256;
            int r = idx >> 3, c = (idx & 7) << 2;
            float4 v = *(const float4*)(g_doch + ((size_t)(b*TDD + d0 + r)) * DHH + kc + c);
            As[c+0][r] = v.x; As[c+1][r] = v.y; As[c+2][r] = v.z; As[c+3][r] = v.w;
        }
        {
            int r = tid >> 3, c = (tid & 7) << 2;
            float4 v = *(const float4*)(g_qryh + ((size_t)(b*TQQ + r)) * DHH + kc + c);
            Bs[c+0][r] = v.x; Bs[c+1][r] = v.y; Bs[c+2][r] = v.z; Bs[c+3][r] = v.w;
        }
        __syncthreads();
#pragma unroll
        for (int kk = 0; kk < 32; kk++){
            ulonglong2 A01 = *(const ulonglong2*)&As[kk][ty*8];
            ulonglong2 A23 = *(const ulonglong2*)&As[kk][ty*8 + 4];
            float2 bq = *(const float2*)&Bs[kk][tx*2];
            unsigned long long q0 = dup2(bq.x), q1 = dup2(bq.y);
            unsigned long long ap[4] = { A01.x, A01.y, A23.x, A23.y };
#pragma unroll
            for (int ip = 0; ip < 4; ip++){
                fma2(acc2[ip][0].u, ap[ip], q0);
                fma2(acc2[ip][1].u, ap[ip], q1);
            }
        }
        __syncthreads();
    }
#pragma unroll
    for (int ip = 0; ip < 4; ip++){
        size_t r0 = (size_t)(b*TDD + d0 + ty*8 + 2*ip);
        *(float2*)(g_scores + r0 * TQQ + tx*2)     = make_float2(acc2[ip][0].f.x, acc2[ip][1].f.x);
        *(float2*)(g_scores + (r0+1) * TQQ + tx*2) = make_float2(acc2[ip][0].f.y, acc2[ip][1].f.y);
    }
}

// ------------------------- fused: column max/sum + beta column-sums + w -------------------------
__global__ __launch_bounds__(256) void k_colbetaw(const int* __restrict__ dlens, const int* __restrict__ qlens){
    int b = blockIdx.x, t = threadIdx.x;
    int q = t & 31, w = t >> 5;
    int dlen = dlens[b], qlen = qlens[b];
    __shared__ float redm[8][32], redc[8][32], redb[8][32];
    __shared__ float cm_s[32];
    const float* sc = g_scores + (size_t)b * TDD * TQQ;

    float lm = -1e30f;
    for (int j = 0; j < 128; j++){ int d = j*8 + w; lm = fmaxf(lm, sc[d*TQQ + q]); }
    redm[w][q] = lm; __syncthreads();
    if (t < 32){
        float m = redm[0][t];
#pragma unroll
        for (int k = 1; k < 8; k++) m = fmaxf(m, redm[k][t]);
        cm_s[t] = m; g_colmax[b*TQQ + t] = m;
    }
    __syncthreads();
    float cm = cm_s[q];

    float csum = 0.f, bacc = 0.f;
    for (int j = 0; j < 128; j++){
        int d = j*8 + w;
        if (d < dlen){
            float v = sc[d*TQQ + q];
            float rm = wmax(v);                    // unmasked row max (matches reference)
            float e = (q < qlen) ? expf(v - rm) : 0.f;
            float rs = wsum(e);
            bacc += e / (rs + EPSF);
            csum += (q < qlen) ? expf(v - cm) : 0.f;
        }
    }
    redc[w][q] = csum; redb[w][q] = bacc; __syncthreads();
    if (t < 32){
        float cs = 0.f, bsum = 0.f;
#pragma unroll
        for (int k = 0; k < 8; k++){ cs += redc[k][t]; bsum += redb[k][t]; }
        g_wq[b*TQQ + t] = (bsum / (float)dlen) / (cs + EPSF);
    }
}

// ------------------------- fused s + probs + vocab sums + argmax + preds -------------------------
// Block b owns batch b entirely: thread-per-doc-row serial q-loop (no shuffles), then a
// block-local argmax over the vocab sums it just produced (tie -> smallest vocab id).
__global__ __launch_bounds__(256) void k_s(const int* __restrict__ docs, const int* __restrict__ dlens,
                                           const int* __restrict__ ans, float* __restrict__ out){
    int b = blockIdx.x, tid = threadIdx.x;
    __shared__ float cm_s[32], w_s[32];
    __shared__ unsigned long long kred[8];
    if (tid < 32){ cm_s[tid] = g_colmax[b*TQQ + tid]; w_s[tid] = g_wq[b*TQQ + tid]; }
    __syncthreads();
    int dlen = dlens[b], a = ans[b];
    const float* sc = g_scores + (size_t)b * TDD * TQQ;
    const int* db = docs + b * TDD;
    float* sums = g_sums + (size_t)b * VV;

    float pacc = 0.f;
#pragma unroll
    for (int i = 0; i < 4; i++){
        int d = i * 256 + tid;
        if (d < dlen){
            const float4* row = (const float4*)(sc + (size_t)d * TQQ);
            float sv = 0.f;
#pragma unroll
            for (int j = 0; j < 8; j++){
                float4 v = row[j];
                sv += expf(v.x - cm_s[j*4+0]) * w_s[j*4+0];   // w_s==0 at invalid q
                sv += expf(v.y - cm_s[j*4+1]) * w_s[j*4+1];
                sv += expf(v.z - cm_s[j*4+2]) * w_s[j*4+2];
                sv += expf(v.w - cm_s[j*4+3]) * w_s[j*4+3];
            }
            int tok = db[d];
            atomicAdd(&sums[tok], sv);
            if (tok == a) pacc += sv;
        }
    }
    if (pacc != 0.f) atomicAdd(&out[b], pacc);
    __threadfence();
    __syncthreads();

    // argmax over this batch's touched vocab slots (f >= 0 -> bits monotone)
    unsigned long long key = 0ull;
#pragma unroll
    for (int i = 0; i < 4; i++){
        int d = i * 256 + tid;
        if (d < dlen){
            int tok = db[d];
            float f = __ldcg(&sums[tok]);
            unsigned long long k2 = ((unsigned long long)__float_as_uint(f) << 32) | (unsigned)(VV - 1 - tok);
            key = (k2 > key) ? k2 : key;
        }
    }
#pragma unroll
    for (int o = 16; o; o >>= 1){
        unsigned long long other = __shfl_xor_sync(0xffffffffu, key, o);
        key = (other > key) ? other : key;
    }
    if ((tid & 31) == 0) kred[tid >> 5] = key;
    __syncthreads();
    if (tid == 0){
        unsigned long long m = kred[0];
#pragma unroll
        for (int k = 1; k < 8; k++) m = (kred[k] > m) ? kred[k] : m;
        out[BB + b] = (float)(VV - 1 - (unsigned)(m & 0xffffffffull));
    }
}

// ------------------------- launcher -------------------------
extern "C" void kernel_launch(void* const* d_in, const int* in_sizes, int n_in,
                              void* d_out, int out_size){
    const int*   docs  = (const int*)d_in[0];
    const int*   dlens = (const int*)d_in[1];
    const int*   qrys  = (const int*)d_in[2];
    const int*   qlens = (const int*)d_in[3];
    const int*   ans   = (const int*)d_in[4];
    const float* emb   = (const float*)d_in[5];
    const float* Wih_f = (const float*)d_in[6];
    const float* Whh_f = (const float*)d_in[7];
    const float* bih_f = (const float*)d_in[8];
    const float* bhh_f = (const float*)d_in[9];
    const float* Wih_b = (const float*)d_in[10];
    const float* Whh_b = (const float*)d_in[11];
    const float* bih_b = (const float*)d_in[12];
    const float* bhh_b = (const float*)d_in[13];
    float* out = (float*)d_out;

    k_reset<<<256, 256>>>(docs, out);                                               // 0
    k_xw<<<dim3(512, 12), 256>>>(docs, 1, dlens, emb, Wih_f, Wih_b, bih_f, bih_b);  // 1
    k_xw<<<dim3(16,  12), 256>>>(qrys, 0, qlens, emb, Wih_f, Wih_b, bih_f, bih_b);  // 2
    k_rnn<<<128, 256>>>(1, TDD, Whh_f, bhh_f, Whh_b, bhh_b, dlens);                 // 3  <- profiled
    k_rnn<<<128, 256>>>(0, TQQ, Whh_f, bhh_f, Whh_b, bhh_b, qlens);                 // 4
    k_scores<<<dim3(TDD/128, BB), 256>>>();
    k_colbetaw<<<BB, 256>>>(dlens, qlens);
    k_s<<<BB, 256>>>(docs, dlens, ans, out);
}